// round 10
// baseline (speedup 1.0000x reference)
#include <cuda_runtime.h>
#include <cuda_bf16.h>
#include <cstdint>

#define N_NODES 80000
#define N_EDGES 1280000
#define HID     64
#define MAXDEG  64

// ---------------- device scratch (no allocations allowed) ----------------
__device__ int   d_cnt[N_NODES];
__device__ __align__(16) int d_col[N_NODES * MAXDEG];   // fixed-width adjacency
__device__ __align__(16) float d_g[N_NODES * HID];      // GEMM out, fp32 natural order
__device__ __align__(16) float d_h[N_NODES * HID];      // agg out, fp32 natural order
__device__ float d_pooled[64 * 64];                     // per-graph means, natural

// ---------------- packed f32x2 helpers ----------------
__device__ __forceinline__ unsigned long long pk2(float lo, float hi) {
    unsigned long long r;
    asm("mov.b64 %0, {%1, %2};" : "=l"(r) : "f"(lo), "f"(hi));
    return r;
}
__device__ __forceinline__ void upk2(unsigned long long v, float& lo, float& hi) {
    asm("mov.b64 {%0, %1}, %2;" : "=f"(lo), "=f"(hi) : "l"(v));
}
__device__ __forceinline__ unsigned long long mul2(unsigned long long x, unsigned long long y) {
    unsigned long long r;
    asm("mul.rn.f32x2 %0, %1, %2;" : "=l"(r) : "l"(x), "l"(y));
    return r;
}
__device__ __forceinline__ void fma2(unsigned long long& a, unsigned long long x,
                                     unsigned long long y) {
    asm("fma.rn.f32x2 %0, %1, %2, %0;" : "+l"(a) : "l"(x), "l"(y));
}
__device__ __forceinline__ void add2(unsigned long long& a, unsigned long long x) {
    asm("add.rn.f32x2 %0, %0, %1;" : "+l"(a) : "l"(x));
}

// ---------------- threefry-2x32 (JAX partitionable semantics) ----------------
__device__ __forceinline__ uint2 threefry_dev(unsigned k0, unsigned k1,
                                              unsigned c0, unsigned c1) {
    unsigned ks2 = k0 ^ k1 ^ 0x1BD11BDAu;
    unsigned x0 = c0 + k0, x1 = c1 + k1;
#define TF_RND(r) { x0 += x1; x1 = __funnelshift_l(x1, x1, (r)); x1 ^= x0; }
    TF_RND(13) TF_RND(15) TF_RND(26) TF_RND(6)   x0 += k1;  x1 += ks2 + 1u;
    TF_RND(17) TF_RND(29) TF_RND(16) TF_RND(24)  x0 += ks2; x1 += k0 + 2u;
    TF_RND(13) TF_RND(15) TF_RND(26) TF_RND(6)   x0 += k0;  x1 += k1 + 3u;
    TF_RND(17) TF_RND(29) TF_RND(16) TF_RND(24)  x0 += k1;  x1 += ks2 + 4u;
    TF_RND(13) TF_RND(15) TF_RND(26) TF_RND(6)   x0 += ks2; x1 += k0 + 5u;
#undef TF_RND
    return make_uint2(x0, x1);
}

// keep = u < 0.7f with u = bitcast((bits>>9)|0x3f800000)-1 = (bits>>9)*2^-23 (exact).
// 0.7f = 11744051*2^-24 -> keep <=> (bits>>9) <= 5872025 <=> bits < 5872026*512.
__device__ __forceinline__ bool keep_elem(unsigned k0, unsigned k1, unsigned idx) {
    uint2 r = threefry_dev(k0, k1, 0u, idx);
    return (r.x ^ r.y) < 3006477312u;
}

// ---------------- adjacency build: zero + direct scatter ----------------
__global__ void k_zero_cnt() {
    int i = blockIdx.x * 256 + threadIdx.x;
    if (i < N_NODES) d_cnt[i] = 0;
}
__global__ void k_scatter(const int* __restrict__ ei) {
    int e = blockIdx.x * 256 + threadIdx.x;
    if (e < N_EDGES) {
        int src = ei[e];
        int dst = ei[N_EDGES + e];
        int pos = atomicAdd(&d_cnt[dst], 1);
        if (pos < MAXDEG) d_col[dst * MAXDEG + pos] = src;
    }
}

// ---------------- Layer-1 GEMM: g = X @ W1 (unscaled), fp32 natural ----------
__global__ void __launch_bounds__(128) k_gemm1(const float* __restrict__ X,
                                               const float* __restrict__ W) {
    __shared__ float  Xs[64][68];
    __shared__ float2 Ws[64][32];
    const int tid = threadIdx.x;
    const int rowBase = blockIdx.x * 64;
    const int tx = tid & 7, ty = tid >> 3;
    const int p0 = tx * 4, r0 = ty * 4;
    unsigned long long acc[4][4];
#pragma unroll
    for (int i = 0; i < 4; i++)
#pragma unroll
        for (int j = 0; j < 4; j++) acc[i][j] = 0ull;

    for (int kb = 0; kb < 128; kb += 64) {
#pragma unroll
        for (int t = 0; t < 32; t++) {
            int idx = tid + t * 128;
            int row = idx >> 6, kk = idx & 63;
            Xs[row][kk] = X[(size_t)(rowBase + row) * 128 + kb + kk];
        }
#pragma unroll
        for (int t = 0; t < 16; t++) {
            int idx = tid + t * 128;
            int kk = idx >> 5, p = idx & 31;
            int krow = kb + kk;
            Ws[kk][p] = make_float2(W[krow * 64 + 2 * p], W[krow * 64 + 2 * p + 1]);
        }
        __syncthreads();
#pragma unroll 8
        for (int kk = 0; kk < 64; ++kk) {
            ulonglong2 wA = *reinterpret_cast<const ulonglong2*>(&Ws[kk][p0]);
            ulonglong2 wB = *reinterpret_cast<const ulonglong2*>(&Ws[kk][p0 + 2]);
#pragma unroll
            for (int i = 0; i < 4; i++) {
                float x = Xs[r0 + i][kk];
                unsigned long long xp;
                asm("mov.b64 %0, {%1, %1};" : "=l"(xp) : "f"(x));
                fma2(acc[i][0], xp, wA.x);
                fma2(acc[i][1], xp, wA.y);
                fma2(acc[i][2], xp, wB.x);
                fma2(acc[i][3], xp, wB.y);
            }
        }
        __syncthreads();
    }
#pragma unroll
    for (int i = 0; i < 4; i++) {
        int row = rowBase + r0 + i;
        float f[8];
#pragma unroll
        for (int j = 0; j < 4; j++) upk2(acc[i][j], f[2 * j], f[2 * j + 1]);
        *reinterpret_cast<float4*>(&d_g[row * 64 + 2 * p0]) =
            make_float4(f[0], f[1], f[2], f[3]);
        *reinterpret_cast<float4*>(&d_g[row * 64 + 2 * p0 + 4]) =
            make_float4(f[4], f[5], f[6], f[7]);
    }
}

// ---------------- Layer-2/3 GEMM: g = (d_h @ W) * dinv, fp32 natural ---------
__global__ void __launch_bounds__(128) k_gemm2(const float* __restrict__ W) {
    __shared__ float  Xs[64][68];
    __shared__ float2 Ws[64][32];
    const float* __restrict__ X = d_h;
    const int tid = threadIdx.x;
    const int rowBase = blockIdx.x * 64;
    const int tx = tid & 7, ty = tid >> 3;
    const int p0 = tx * 4, r0 = ty * 4;
    unsigned long long acc[4][4];
#pragma unroll
    for (int i = 0; i < 4; i++)
#pragma unroll
        for (int j = 0; j < 4; j++) acc[i][j] = 0ull;

#pragma unroll
    for (int t = 0; t < 32; t++) {
        int idx = tid + t * 128;
        int row = idx >> 6, kk = idx & 63;
        Xs[row][kk] = X[(size_t)(rowBase + row) * 64 + kk];
    }
#pragma unroll
    for (int t = 0; t < 16; t++) {
        int idx = tid + t * 128;
        int kk = idx >> 5, p = idx & 31;
        Ws[kk][p] = make_float2(W[kk * 64 + 2 * p], W[kk * 64 + 2 * p + 1]);
    }
    __syncthreads();
#pragma unroll 8
    for (int kk = 0; kk < 64; ++kk) {
        ulonglong2 wA = *reinterpret_cast<const ulonglong2*>(&Ws[kk][p0]);
        ulonglong2 wB = *reinterpret_cast<const ulonglong2*>(&Ws[kk][p0 + 2]);
#pragma unroll
        for (int i = 0; i < 4; i++) {
            float x = Xs[r0 + i][kk];
            unsigned long long xp;
            asm("mov.b64 %0, {%1, %1};" : "=l"(xp) : "f"(x));
            fma2(acc[i][0], xp, wA.x);
            fma2(acc[i][1], xp, wA.y);
            fma2(acc[i][2], xp, wB.x);
            fma2(acc[i][3], xp, wB.y);
        }
    }
#pragma unroll
    for (int i = 0; i < 4; i++) {
        int row = rowBase + r0 + i;
        float di = rsqrtf((float)d_cnt[row] + 1.0f);
        float f[8];
#pragma unroll
        for (int j = 0; j < 4; j++) {
            float lo, hi;
            upk2(acc[i][j], lo, hi);
            f[2 * j] = lo * di; f[2 * j + 1] = hi * di;
        }
        *reinterpret_cast<float4*>(&d_g[row * 64 + 2 * p0]) =
            make_float4(f[0], f[1], f[2], f[3]);
        *reinterpret_cast<float4*>(&d_g[row * 64 + 2 * p0 + 4]) =
            make_float4(f[4], f[5], f[6], f[7]);
    }
}

// ---------------- Aggregation + bias + ReLU + inline dropout ------------------
// 2 nodes per warp: lanes 0-15 -> node 2w, lanes 16-31 -> node 2w+1.
// Each lane owns 4 contiguous channels (one ulonglong2 = 2 packed f32x2).
template <bool FIRST>
__global__ void __launch_bounds__(256) k_agg(const float* __restrict__ bias,
                                             unsigned k0, unsigned k1) {
    int gw = (blockIdx.x * 256 + threadIdx.x) >> 5;
    int lane = threadIdx.x & 31;
    int v = gw * 2 + (lane >> 4);
    int c0 = (lane & 15) * 4;

    int cntv = d_cnt[v];
    int deg = min(cntv, MAXDEG);
    float dv = rsqrtf((float)cntv + 1.0f);
    const int* __restrict__ cols = &d_col[(size_t)v * MAXDEG];

    ulonglong2 self = *reinterpret_cast<const ulonglong2*>(&d_g[v * 64 + c0]);
    unsigned long long acc0 = self.x, acc1 = self.y;
    if (FIRST) {
        unsigned long long dvp = pk2(dv, dv);
        acc0 = mul2(acc0, dvp);
        acc1 = mul2(acc1, dvp);
    }

    int j = 0;
    if (FIRST) {
        for (; j + 4 <= deg; j += 4) {
            int4 c4 = *reinterpret_cast<const int4*>(&cols[j]);
            ulonglong2 t0 = *reinterpret_cast<const ulonglong2*>(&d_g[c4.x * 64 + c0]);
            ulonglong2 t1 = *reinterpret_cast<const ulonglong2*>(&d_g[c4.y * 64 + c0]);
            ulonglong2 t2 = *reinterpret_cast<const ulonglong2*>(&d_g[c4.z * 64 + c0]);
            ulonglong2 t3 = *reinterpret_cast<const ulonglong2*>(&d_g[c4.w * 64 + c0]);
            float du0 = rsqrtf((float)d_cnt[c4.x] + 1.0f);
            float du1 = rsqrtf((float)d_cnt[c4.y] + 1.0f);
            float du2 = rsqrtf((float)d_cnt[c4.z] + 1.0f);
            float du3 = rsqrtf((float)d_cnt[c4.w] + 1.0f);
            unsigned long long d0 = pk2(du0, du0), d1 = pk2(du1, du1);
            unsigned long long d2 = pk2(du2, du2), d3 = pk2(du3, du3);
            fma2(acc0, t0.x, d0); fma2(acc1, t0.y, d0);
            fma2(acc0, t1.x, d1); fma2(acc1, t1.y, d1);
            fma2(acc0, t2.x, d2); fma2(acc1, t2.y, d2);
            fma2(acc0, t3.x, d3); fma2(acc1, t3.y, d3);
        }
        for (; j < deg; ++j) {
            int u = cols[j];
            ulonglong2 t = *reinterpret_cast<const ulonglong2*>(&d_g[u * 64 + c0]);
            float du = rsqrtf((float)d_cnt[u] + 1.0f);
            unsigned long long dp = pk2(du, du);
            fma2(acc0, t.x, dp); fma2(acc1, t.y, dp);
        }
    } else {
        for (; j + 8 <= deg; j += 8) {
            int4 ca = *reinterpret_cast<const int4*>(&cols[j]);
            int4 cb = *reinterpret_cast<const int4*>(&cols[j + 4]);
            ulonglong2 t0 = *reinterpret_cast<const ulonglong2*>(&d_g[ca.x * 64 + c0]);
            ulonglong2 t1 = *reinterpret_cast<const ulonglong2*>(&d_g[ca.y * 64 + c0]);
            ulonglong2 t2 = *reinterpret_cast<const ulonglong2*>(&d_g[ca.z * 64 + c0]);
            ulonglong2 t3 = *reinterpret_cast<const ulonglong2*>(&d_g[ca.w * 64 + c0]);
            ulonglong2 t4 = *reinterpret_cast<const ulonglong2*>(&d_g[cb.x * 64 + c0]);
            ulonglong2 t5 = *reinterpret_cast<const ulonglong2*>(&d_g[cb.y * 64 + c0]);
            ulonglong2 t6 = *reinterpret_cast<const ulonglong2*>(&d_g[cb.z * 64 + c0]);
            ulonglong2 t7 = *reinterpret_cast<const ulonglong2*>(&d_g[cb.w * 64 + c0]);
            add2(acc0, t0.x); add2(acc1, t0.y);
            add2(acc0, t1.x); add2(acc1, t1.y);
            add2(acc0, t2.x); add2(acc1, t2.y);
            add2(acc0, t3.x); add2(acc1, t3.y);
            add2(acc0, t4.x); add2(acc1, t4.y);
            add2(acc0, t5.x); add2(acc1, t5.y);
            add2(acc0, t6.x); add2(acc1, t6.y);
            add2(acc0, t7.x); add2(acc1, t7.y);
        }
        for (; j + 4 <= deg; j += 4) {
            int4 c4 = *reinterpret_cast<const int4*>(&cols[j]);
            ulonglong2 t0 = *reinterpret_cast<const ulonglong2*>(&d_g[c4.x * 64 + c0]);
            ulonglong2 t1 = *reinterpret_cast<const ulonglong2*>(&d_g[c4.y * 64 + c0]);
            ulonglong2 t2 = *reinterpret_cast<const ulonglong2*>(&d_g[c4.z * 64 + c0]);
            ulonglong2 t3 = *reinterpret_cast<const ulonglong2*>(&d_g[c4.w * 64 + c0]);
            add2(acc0, t0.x); add2(acc1, t0.y);
            add2(acc0, t1.x); add2(acc1, t1.y);
            add2(acc0, t2.x); add2(acc1, t2.y);
            add2(acc0, t3.x); add2(acc1, t3.y);
        }
        for (; j < deg; ++j) {
            int u = cols[j];
            ulonglong2 t = *reinterpret_cast<const ulonglong2*>(&d_g[u * 64 + c0]);
            add2(acc0, t.x); add2(acc1, t.y);
        }
    }

    float a0, a1, a2, a3;
    upk2(acc0, a0, a1);
    upk2(acc1, a2, a3);
    float4 b4 = *reinterpret_cast<const float4*>(&bias[c0]);
    float o0 = fmaxf(fmaf(dv, a0, b4.x), 0.0f);
    float o1 = fmaxf(fmaf(dv, a1, b4.y), 0.0f);
    float o2 = fmaxf(fmaf(dv, a2, b4.z), 0.0f);
    float o3 = fmaxf(fmaf(dv, a3, b4.w), 0.0f);

    unsigned i0 = (unsigned)v * 64u + (unsigned)c0;
    const float inv_keep = 1.0f / 0.7f;
    float4 hv;
    hv.x = keep_elem(k0, k1, i0)      ? o0 * inv_keep : 0.0f;
    hv.y = keep_elem(k0, k1, i0 + 1u) ? o1 * inv_keep : 0.0f;
    hv.z = keep_elem(k0, k1, i0 + 2u) ? o2 * inv_keep : 0.0f;
    hv.w = keep_elem(k0, k1, i0 + 3u) ? o3 * inv_keep : 0.0f;
    *reinterpret_cast<float4*>(&d_h[v * 64 + c0]) = hv;
}

// ---------------- Mean pool per graph (natural order) ----------------
__global__ void k_pool(const int* __restrict__ batch) {
    __shared__ int sse[2];
    __shared__ float2 red[8][32];
    int g = blockIdx.x;
    int tid = threadIdx.x;
    if (tid < 2) {
        int target = g + tid;
        int lo = 0, hi = N_NODES;
        while (lo < hi) { int m = (lo + hi) >> 1; if (batch[m] < target) lo = m + 1; else hi = m; }
        sse[tid] = lo;
    }
    __syncthreads();
    int start = sse[0], end = sse[1];
    int p = tid & 31, grp = tid >> 5;
    float2 acc = make_float2(0.f, 0.f);
    for (int v = start + grp; v < end; v += 8) {
        float2 t = *reinterpret_cast<const float2*>(&d_h[v * 64 + 2 * p]);
        acc.x += t.x; acc.y += t.y;
    }
    red[grp][p] = acc;
    __syncthreads();
    if (grp == 0) {
#pragma unroll
        for (int i = 1; i < 8; i++) { acc.x += red[i][p].x; acc.y += red[i][p].y; }
        float cnt = fmaxf((float)(end - start), 1.0f);
        *reinterpret_cast<float2*>(&d_pooled[g * 64 + 2 * p]) =
            make_float2(acc.x / cnt, acc.y / cnt);
    }
}

// ---------------- MLP head (natural order) ----------------
__global__ void k_head(const float* __restrict__ Wm1, const float* __restrict__ bm1,
                       const float* __restrict__ Wm2, const float* __restrict__ bm2,
                       float* __restrict__ out, unsigned k0, unsigned k1) {
    __shared__ float Ps[64][64];
    __shared__ float Ws[64][64];
    int tid = threadIdx.x;
    for (int idx = tid; idx < 4096; idx += 1024)
        Ps[idx >> 6][idx & 63] = d_pooled[idx];
    for (int idx = tid; idx < 4096; idx += 1024)
        Ws[idx >> 6][idx & 63] = Wm1[idx];
    __syncthreads();

    int c = tid & 63, gb = tid >> 6;
    float mv[2][2];
#pragma unroll
    for (int halfg = 0; halfg < 2; ++halfg) {
        int g = gb + halfg * 16;
        float mA = bm1[c], mB = bm1[c];
#pragma unroll
        for (int s = 0; s < 64; s++) {
            mA = fmaf(Ps[g][s], Ws[s][c], mA);
            mB = fmaf(Ps[g + 32][s], Ws[s][c], mB);
        }
        mA = fmaxf(mA, 0.0f);
        mB = fmaxf(mB, 0.0f);
        unsigned iA = (unsigned)g * 64u + (unsigned)c;
        unsigned iB = (unsigned)(g + 32) * 64u + (unsigned)c;
        const float inv_keep = 1.0f / 0.7f;
        mv[halfg][0] = keep_elem(k0, k1, iA) ? mA * inv_keep : 0.0f;
        mv[halfg][1] = keep_elem(k0, k1, iB) ? mB * inv_keep : 0.0f;
    }
    __syncthreads();
#pragma unroll
    for (int halfg = 0; halfg < 2; ++halfg) {
        int g = gb + halfg * 16;
        Ps[g][c] = mv[halfg][0];
        Ps[g + 32][c] = mv[halfg][1];
    }
    __syncthreads();
    if (tid < 64) {
        float o = bm2[0];
#pragma unroll
        for (int cc = 0; cc < 64; ++cc) o = fmaf(Ps[tid][cc], Wm2[cc], o);
        out[tid] = o;
    }
}

// ---------------- host threefry (key splitting) ----------------
static inline void tf_host(unsigned k0, unsigned k1, unsigned c0, unsigned c1,
                           unsigned& o0, unsigned& o1) {
    unsigned ks2 = k0 ^ k1 ^ 0x1BD11BDAu;
    unsigned x0 = c0 + k0, x1 = c1 + k1;
#define HROT(x, r) (((x) << (r)) | ((x) >> (32 - (r))))
#define HRND(r) { x0 += x1; x1 = HROT(x1, r); x1 ^= x0; }
    HRND(13) HRND(15) HRND(26) HRND(6)   x0 += k1;  x1 += ks2 + 1u;
    HRND(17) HRND(29) HRND(16) HRND(24)  x0 += ks2; x1 += k0 + 2u;
    HRND(13) HRND(15) HRND(26) HRND(6)   x0 += k0;  x1 += k1 + 3u;
    HRND(17) HRND(29) HRND(16) HRND(24)  x0 += k1;  x1 += ks2 + 4u;
    HRND(13) HRND(15) HRND(26) HRND(6)   x0 += ks2; x1 += k0 + 5u;
#undef HRND
#undef HROT
    o0 = x0; o1 = x1;
}

extern "C" void kernel_launch(void* const* d_in, const int* in_sizes, int n_in,
                              void* d_out, int out_size) {
    const float* x     = (const float*)d_in[0];
    const int*   ei    = (const int*)d_in[1];
    const int*   batch = (const int*)d_in[2];
    const float* W1 = (const float*)d_in[3];  const float* b1 = (const float*)d_in[4];
    const float* W2 = (const float*)d_in[5];  const float* b2 = (const float*)d_in[6];
    const float* W3 = (const float*)d_in[7];  const float* b3 = (const float*)d_in[8];
    const float* Wm1 = (const float*)d_in[9]; const float* bm1 = (const float*)d_in[10];
    const float* Wm2 = (const float*)d_in[11];const float* bm2 = (const float*)d_in[12];
    float* out = (float*)d_out;

    // split(key(42), 4) partitionable: dk[i] = threefry((0,42), (0, i))
    unsigned dk[4][2];
    for (unsigned i = 0; i < 4; i++)
        tf_host(0u, 42u, 0u, i, dk[i][0], dk[i][1]);

    static cudaStream_t s_csr = nullptr;
    static cudaEvent_t ev_root = nullptr, ev_csr = nullptr;
    if (!s_csr) {
        cudaStreamCreateWithFlags(&s_csr, cudaStreamNonBlocking);
        cudaEventCreateWithFlags(&ev_root, cudaEventDisableTiming);
        cudaEventCreateWithFlags(&ev_csr, cudaEventDisableTiming);
    }

    const int NB64 = N_NODES / 64;                          // 1250
    const int AGG_BLOCKS = (N_NODES / 2 * 32 + 255) / 256;  // 5000 (2 nodes/warp)

    cudaEventRecord(ev_root, (cudaStream_t)0);
    cudaStreamWaitEvent(s_csr, ev_root, 0);

    // Adjacency build on side stream, overlapped with layer-1 GEMM.
    k_zero_cnt<<<(N_NODES + 255) / 256, 256, 0, s_csr>>>();
    k_scatter<<<(N_EDGES + 255) / 256, 256, 0, s_csr>>>(ei);
    cudaEventRecord(ev_csr, s_csr);

    k_gemm1<<<NB64, 128>>>(x, W1);

    cudaStreamWaitEvent((cudaStream_t)0, ev_csr, 0);

    k_agg<true><<<AGG_BLOCKS, 256>>>(b1, dk[0][0], dk[0][1]);
    k_gemm2<<<NB64, 128>>>(W2);
    k_agg<false><<<AGG_BLOCKS, 256>>>(b2, dk[1][0], dk[1][1]);
    k_gemm2<<<NB64, 128>>>(W3);
    k_agg<false><<<AGG_BLOCKS, 256>>>(b3, dk[2][0], dk[2][1]);

    k_pool<<<64, 256>>>(batch);
    k_head<<<1, 1024>>>(Wm1, bm1, Wm2, bm2, out, dk[3][0], dk[3][1]);

    (void)in_sizes; (void)n_in; (void)out_size;
}

// round 11
// speedup vs baseline: 1.0613x; 1.0613x over previous
#include <cuda_runtime.h>
#include <cuda_bf16.h>
#include <cstdint>

#define N_NODES 80000
#define N_EDGES 1280000
#define HID     64
#define MAXDEG  64

// ---------------- device scratch (no allocations allowed) ----------------
__device__ int   d_cnt[N_NODES];
__device__ __align__(16) int d_col[N_NODES * MAXDEG];   // fixed-width adjacency
__device__ __align__(16) float d_g[N_NODES * HID];      // GEMM out, fp32 natural order
__device__ __align__(16) float d_h[N_NODES * HID];      // agg out, fp32 natural order
__device__ float d_pooled[64 * 64];                     // per-graph means, natural

// ---------------- threefry-2x32 (JAX partitionable semantics) ----------------
__device__ __forceinline__ uint2 threefry_dev(unsigned k0, unsigned k1,
                                              unsigned c0, unsigned c1) {
    unsigned ks2 = k0 ^ k1 ^ 0x1BD11BDAu;
    unsigned x0 = c0 + k0, x1 = c1 + k1;
#define TF_RND(r) { x0 += x1; x1 = __funnelshift_l(x1, x1, (r)); x1 ^= x0; }
    TF_RND(13) TF_RND(15) TF_RND(26) TF_RND(6)   x0 += k1;  x1 += ks2 + 1u;
    TF_RND(17) TF_RND(29) TF_RND(16) TF_RND(24)  x0 += ks2; x1 += k0 + 2u;
    TF_RND(13) TF_RND(15) TF_RND(26) TF_RND(6)   x0 += k0;  x1 += k1 + 3u;
    TF_RND(17) TF_RND(29) TF_RND(16) TF_RND(24)  x0 += k1;  x1 += ks2 + 4u;
    TF_RND(13) TF_RND(15) TF_RND(26) TF_RND(6)   x0 += ks2; x1 += k0 + 5u;
#undef TF_RND
    return make_uint2(x0, x1);
}

// keep = u < 0.7f with u = bitcast((bits>>9)|0x3f800000)-1 = (bits>>9)*2^-23 (exact).
// 0.7f = 11744051*2^-24 -> keep <=> (bits>>9) <= 5872025 <=> bits < 5872026*512.
__device__ __forceinline__ bool keep_elem(unsigned k0, unsigned k1, unsigned idx) {
    uint2 r = threefry_dev(k0, k1, 0u, idx);
    return (r.x ^ r.y) < 3006477312u;
}

// ---------------- adjacency build: zero + direct scatter ----------------
__global__ void k_zero_cnt() {
    int i = blockIdx.x * 256 + threadIdx.x;
    if (i < N_NODES) d_cnt[i] = 0;
}
__global__ void k_scatter(const int* __restrict__ ei) {
    int e = blockIdx.x * 256 + threadIdx.x;
    if (e < N_EDGES) {
        int src = ei[e];
        int dst = ei[N_EDGES + e];
        int pos = atomicAdd(&d_cnt[dst], 1);
        if (pos < MAXDEG) d_col[dst * MAXDEG + pos] = src;
    }
}

// ---------------- Layer-1 GEMM: g = X @ W1 (unscaled), fp32 natural ----------
__global__ void __launch_bounds__(128) k_gemm1(const float* __restrict__ X,
                                               const float* __restrict__ W) {
    __shared__ float  Xs[64][68];
    __shared__ float2 Ws[64][32];
    const int tid = threadIdx.x;
    const int rowBase = blockIdx.x * 64;
    const int tx = tid & 7, ty = tid >> 3;
    const int p0 = tx * 4, r0 = ty * 4;
    unsigned long long acc[4][4];
#pragma unroll
    for (int i = 0; i < 4; i++)
#pragma unroll
        for (int j = 0; j < 4; j++) acc[i][j] = 0ull;

    for (int kb = 0; kb < 128; kb += 64) {
#pragma unroll
        for (int t = 0; t < 32; t++) {
            int idx = tid + t * 128;
            int row = idx >> 6, kk = idx & 63;
            Xs[row][kk] = X[(size_t)(rowBase + row) * 128 + kb + kk];
        }
#pragma unroll
        for (int t = 0; t < 16; t++) {
            int idx = tid + t * 128;
            int kk = idx >> 5, p = idx & 31;
            int krow = kb + kk;
            Ws[kk][p] = make_float2(W[krow * 64 + 2 * p], W[krow * 64 + 2 * p + 1]);
        }
        __syncthreads();
#pragma unroll 8
        for (int kk = 0; kk < 64; ++kk) {
            ulonglong2 wA = *reinterpret_cast<const ulonglong2*>(&Ws[kk][p0]);
            ulonglong2 wB = *reinterpret_cast<const ulonglong2*>(&Ws[kk][p0 + 2]);
#pragma unroll
            for (int i = 0; i < 4; i++) {
                float x = Xs[r0 + i][kk];
                unsigned long long xp;
                asm("mov.b64 %0, {%1, %1};" : "=l"(xp) : "f"(x));
                asm("fma.rn.f32x2 %0, %1, %2, %0;" : "+l"(acc[i][0]) : "l"(xp), "l"(wA.x));
                asm("fma.rn.f32x2 %0, %1, %2, %0;" : "+l"(acc[i][1]) : "l"(xp), "l"(wA.y));
                asm("fma.rn.f32x2 %0, %1, %2, %0;" : "+l"(acc[i][2]) : "l"(xp), "l"(wB.x));
                asm("fma.rn.f32x2 %0, %1, %2, %0;" : "+l"(acc[i][3]) : "l"(xp), "l"(wB.y));
            }
        }
        __syncthreads();
    }
#pragma unroll
    for (int i = 0; i < 4; i++) {
        int row = rowBase + r0 + i;
        float f[8];
#pragma unroll
        for (int j = 0; j < 4; j++)
            asm("mov.b64 {%0, %1}, %2;" : "=f"(f[2 * j]), "=f"(f[2 * j + 1]) : "l"(acc[i][j]));
        *reinterpret_cast<float4*>(&d_g[row * 64 + 2 * p0]) =
            make_float4(f[0], f[1], f[2], f[3]);
        *reinterpret_cast<float4*>(&d_g[row * 64 + 2 * p0 + 4]) =
            make_float4(f[4], f[5], f[6], f[7]);
    }
}

// ---------------- Layer-2/3 GEMM: g = (d_h @ W) * dinv, fp32 natural ---------
__global__ void __launch_bounds__(128) k_gemm2(const float* __restrict__ W) {
    __shared__ float  Xs[64][68];
    __shared__ float2 Ws[64][32];
    const float* __restrict__ X = d_h;
    const int tid = threadIdx.x;
    const int rowBase = blockIdx.x * 64;
    const int tx = tid & 7, ty = tid >> 3;
    const int p0 = tx * 4, r0 = ty * 4;
    unsigned long long acc[4][4];
#pragma unroll
    for (int i = 0; i < 4; i++)
#pragma unroll
        for (int j = 0; j < 4; j++) acc[i][j] = 0ull;

#pragma unroll
    for (int t = 0; t < 32; t++) {
        int idx = tid + t * 128;
        int row = idx >> 6, kk = idx & 63;
        Xs[row][kk] = X[(size_t)(rowBase + row) * 64 + kk];
    }
#pragma unroll
    for (int t = 0; t < 16; t++) {
        int idx = tid + t * 128;
        int kk = idx >> 5, p = idx & 31;
        Ws[kk][p] = make_float2(W[kk * 64 + 2 * p], W[kk * 64 + 2 * p + 1]);
    }
    __syncthreads();
#pragma unroll 8
    for (int kk = 0; kk < 64; ++kk) {
        ulonglong2 wA = *reinterpret_cast<const ulonglong2*>(&Ws[kk][p0]);
        ulonglong2 wB = *reinterpret_cast<const ulonglong2*>(&Ws[kk][p0 + 2]);
#pragma unroll
        for (int i = 0; i < 4; i++) {
            float x = Xs[r0 + i][kk];
            unsigned long long xp;
            asm("mov.b64 %0, {%1, %1};" : "=l"(xp) : "f"(x));
            asm("fma.rn.f32x2 %0, %1, %2, %0;" : "+l"(acc[i][0]) : "l"(xp), "l"(wA.x));
            asm("fma.rn.f32x2 %0, %1, %2, %0;" : "+l"(acc[i][1]) : "l"(xp), "l"(wA.y));
            asm("fma.rn.f32x2 %0, %1, %2, %0;" : "+l"(acc[i][2]) : "l"(xp), "l"(wB.x));
            asm("fma.rn.f32x2 %0, %1, %2, %0;" : "+l"(acc[i][3]) : "l"(xp), "l"(wB.y));
        }
    }
#pragma unroll
    for (int i = 0; i < 4; i++) {
        int row = rowBase + r0 + i;
        float di = rsqrtf((float)d_cnt[row] + 1.0f);
        float f[8];
#pragma unroll
        for (int j = 0; j < 4; j++) {
            float lo, hi;
            asm("mov.b64 {%0, %1}, %2;" : "=f"(lo), "=f"(hi) : "l"(acc[i][j]));
            f[2 * j] = lo * di; f[2 * j + 1] = hi * di;
        }
        *reinterpret_cast<float4*>(&d_g[row * 64 + 2 * p0]) =
            make_float4(f[0], f[1], f[2], f[3]);
        *reinterpret_cast<float4*>(&d_g[row * 64 + 2 * p0 + 4]) =
            make_float4(f[4], f[5], f[6], f[7]);
    }
}

// ---------------- Aggregation + bias + ReLU + inline dropout ------------------
// Round-9 proven body; only changes: int4 adjacency loads + integer dropout compare.
// 2 nodes per warp: lanes 0-15 -> node 2w, lanes 16-31 -> node 2w+1.
template <bool FIRST>
__global__ void __launch_bounds__(256) k_agg(const float* __restrict__ bias,
                                             unsigned k0, unsigned k1) {
    int gw = (blockIdx.x * 256 + threadIdx.x) >> 5;
    int lane = threadIdx.x & 31;
    int v = gw * 2 + (lane >> 4);
    int c0 = (lane & 15) * 4;

    int cntv = d_cnt[v];
    int deg = min(cntv, MAXDEG);
    float dv = rsqrtf((float)cntv + 1.0f);
    const int* __restrict__ cols = &d_col[(size_t)v * MAXDEG];

    float4 acc = *reinterpret_cast<const float4*>(&d_g[v * 64 + c0]);
    if (FIRST) { acc.x *= dv; acc.y *= dv; acc.z *= dv; acc.w *= dv; }

    int j = 0;
    for (; j + 4 <= deg; j += 4) {
        int4 c4 = *reinterpret_cast<const int4*>(&cols[j]);
        float4 t0 = *reinterpret_cast<const float4*>(&d_g[c4.x * 64 + c0]);
        float4 t1 = *reinterpret_cast<const float4*>(&d_g[c4.y * 64 + c0]);
        float4 t2 = *reinterpret_cast<const float4*>(&d_g[c4.z * 64 + c0]);
        float4 t3 = *reinterpret_cast<const float4*>(&d_g[c4.w * 64 + c0]);
        if (FIRST) {
            float du0 = rsqrtf((float)d_cnt[c4.x] + 1.0f);
            float du1 = rsqrtf((float)d_cnt[c4.y] + 1.0f);
            float du2 = rsqrtf((float)d_cnt[c4.z] + 1.0f);
            float du3 = rsqrtf((float)d_cnt[c4.w] + 1.0f);
            acc.x = fmaf(t0.x, du0, acc.x); acc.y = fmaf(t0.y, du0, acc.y);
            acc.z = fmaf(t0.z, du0, acc.z); acc.w = fmaf(t0.w, du0, acc.w);
            acc.x = fmaf(t1.x, du1, acc.x); acc.y = fmaf(t1.y, du1, acc.y);
            acc.z = fmaf(t1.z, du1, acc.z); acc.w = fmaf(t1.w, du1, acc.w);
            acc.x = fmaf(t2.x, du2, acc.x); acc.y = fmaf(t2.y, du2, acc.y);
            acc.z = fmaf(t2.z, du2, acc.z); acc.w = fmaf(t2.w, du2, acc.w);
            acc.x = fmaf(t3.x, du3, acc.x); acc.y = fmaf(t3.y, du3, acc.y);
            acc.z = fmaf(t3.z, du3, acc.z); acc.w = fmaf(t3.w, du3, acc.w);
        } else {
            acc.x += (t0.x + t1.x) + (t2.x + t3.x);
            acc.y += (t0.y + t1.y) + (t2.y + t3.y);
            acc.z += (t0.z + t1.z) + (t2.z + t3.z);
            acc.w += (t0.w + t1.w) + (t2.w + t3.w);
        }
    }
    for (; j < deg; ++j) {
        int u = cols[j];
        float4 t = *reinterpret_cast<const float4*>(&d_g[u * 64 + c0]);
        if (FIRST) {
            float du = rsqrtf((float)d_cnt[u] + 1.0f);
            acc.x = fmaf(t.x, du, acc.x); acc.y = fmaf(t.y, du, acc.y);
            acc.z = fmaf(t.z, du, acc.z); acc.w = fmaf(t.w, du, acc.w);
        } else {
            acc.x += t.x; acc.y += t.y; acc.z += t.z; acc.w += t.w;
        }
    }

    float4 b4 = *reinterpret_cast<const float4*>(&bias[c0]);
    float o0 = fmaxf(fmaf(dv, acc.x, b4.x), 0.0f);
    float o1 = fmaxf(fmaf(dv, acc.y, b4.y), 0.0f);
    float o2 = fmaxf(fmaf(dv, acc.z, b4.z), 0.0f);
    float o3 = fmaxf(fmaf(dv, acc.w, b4.w), 0.0f);

    unsigned i0 = (unsigned)v * 64u + (unsigned)c0;
    const float inv_keep = 1.0f / 0.7f;
    float4 hv;
    hv.x = keep_elem(k0, k1, i0)      ? o0 * inv_keep : 0.0f;
    hv.y = keep_elem(k0, k1, i0 + 1u) ? o1 * inv_keep : 0.0f;
    hv.z = keep_elem(k0, k1, i0 + 2u) ? o2 * inv_keep : 0.0f;
    hv.w = keep_elem(k0, k1, i0 + 3u) ? o3 * inv_keep : 0.0f;
    *reinterpret_cast<float4*>(&d_h[v * 64 + c0]) = hv;
}

// ---------------- Mean pool per graph (natural order) ----------------
__global__ void k_pool(const int* __restrict__ batch) {
    __shared__ int sse[2];
    __shared__ float2 red[8][32];
    int g = blockIdx.x;
    int tid = threadIdx.x;
    if (tid < 2) {
        int target = g + tid;
        int lo = 0, hi = N_NODES;
        while (lo < hi) { int m = (lo + hi) >> 1; if (batch[m] < target) lo = m + 1; else hi = m; }
        sse[tid] = lo;
    }
    __syncthreads();
    int start = sse[0], end = sse[1];
    int p = tid & 31, grp = tid >> 5;
    float2 acc = make_float2(0.f, 0.f);
    for (int v = start + grp; v < end; v += 8) {
        float2 t = *reinterpret_cast<const float2*>(&d_h[v * 64 + 2 * p]);
        acc.x += t.x; acc.y += t.y;
    }
    red[grp][p] = acc;
    __syncthreads();
    if (grp == 0) {
#pragma unroll
        for (int i = 1; i < 8; i++) { acc.x += red[i][p].x; acc.y += red[i][p].y; }
        float cnt = fmaxf((float)(end - start), 1.0f);
        *reinterpret_cast<float2*>(&d_pooled[g * 64 + 2 * p]) =
            make_float2(acc.x / cnt, acc.y / cnt);
    }
}

// ---------------- MLP head (natural order) ----------------
__global__ void k_head(const float* __restrict__ Wm1, const float* __restrict__ bm1,
                       const float* __restrict__ Wm2, const float* __restrict__ bm2,
                       float* __restrict__ out, unsigned k0, unsigned k1) {
    __shared__ float Ps[64][64];
    __shared__ float Ws[64][64];
    int tid = threadIdx.x;
    for (int idx = tid; idx < 4096; idx += 1024)
        Ps[idx >> 6][idx & 63] = d_pooled[idx];
    for (int idx = tid; idx < 4096; idx += 1024)
        Ws[idx >> 6][idx & 63] = Wm1[idx];
    __syncthreads();

    int c = tid & 63, gb = tid >> 6;
    float mv[2][2];
#pragma unroll
    for (int halfg = 0; halfg < 2; ++halfg) {
        int g = gb + halfg * 16;
        float mA = bm1[c], mB = bm1[c];
#pragma unroll
        for (int s = 0; s < 64; s++) {
            mA = fmaf(Ps[g][s], Ws[s][c], mA);
            mB = fmaf(Ps[g + 32][s], Ws[s][c], mB);
        }
        mA = fmaxf(mA, 0.0f);
        mB = fmaxf(mB, 0.0f);
        unsigned iA = (unsigned)g * 64u + (unsigned)c;
        unsigned iB = (unsigned)(g + 32) * 64u + (unsigned)c;
        const float inv_keep = 1.0f / 0.7f;
        mv[halfg][0] = keep_elem(k0, k1, iA) ? mA * inv_keep : 0.0f;
        mv[halfg][1] = keep_elem(k0, k1, iB) ? mB * inv_keep : 0.0f;
    }
    __syncthreads();
#pragma unroll
    for (int halfg = 0; halfg < 2; ++halfg) {
        int g = gb + halfg * 16;
        Ps[g][c] = mv[halfg][0];
        Ps[g + 32][c] = mv[halfg][1];
    }
    __syncthreads();
    if (tid < 64) {
        float o = bm2[0];
#pragma unroll
        for (int cc = 0; cc < 64; ++cc) o = fmaf(Ps[tid][cc], Wm2[cc], o);
        out[tid] = o;
    }
}

// ---------------- host threefry (key splitting) ----------------
static inline void tf_host(unsigned k0, unsigned k1, unsigned c0, unsigned c1,
                           unsigned& o0, unsigned& o1) {
    unsigned ks2 = k0 ^ k1 ^ 0x1BD11BDAu;
    unsigned x0 = c0 + k0, x1 = c1 + k1;
#define HROT(x, r) (((x) << (r)) | ((x) >> (32 - (r))))
#define HRND(r) { x0 += x1; x1 = HROT(x1, r); x1 ^= x0; }
    HRND(13) HRND(15) HRND(26) HRND(6)   x0 += k1;  x1 += ks2 + 1u;
    HRND(17) HRND(29) HRND(16) HRND(24)  x0 += ks2; x1 += k0 + 2u;
    HRND(13) HRND(15) HRND(26) HRND(6)   x0 += k0;  x1 += k1 + 3u;
    HRND(17) HRND(29) HRND(16) HRND(24)  x0 += k1;  x1 += ks2 + 4u;
    HRND(13) HRND(15) HRND(26) HRND(6)   x0 += ks2; x1 += k0 + 5u;
#undef HRND
#undef HROT
    o0 = x0; o1 = x1;
}

extern "C" void kernel_launch(void* const* d_in, const int* in_sizes, int n_in,
                              void* d_out, int out_size) {
    const float* x     = (const float*)d_in[0];
    const int*   ei    = (const int*)d_in[1];
    const int*   batch = (const int*)d_in[2];
    const float* W1 = (const float*)d_in[3];  const float* b1 = (const float*)d_in[4];
    const float* W2 = (const float*)d_in[5];  const float* b2 = (const float*)d_in[6];
    const float* W3 = (const float*)d_in[7];  const float* b3 = (const float*)d_in[8];
    const float* Wm1 = (const float*)d_in[9]; const float* bm1 = (const float*)d_in[10];
    const float* Wm2 = (const float*)d_in[11];const float* bm2 = (const float*)d_in[12];
    float* out = (float*)d_out;

    // split(key(42), 4) partitionable: dk[i] = threefry((0,42), (0, i))
    unsigned dk[4][2];
    for (unsigned i = 0; i < 4; i++)
        tf_host(0u, 42u, 0u, i, dk[i][0], dk[i][1]);

    static cudaStream_t s_csr = nullptr;
    static cudaEvent_t ev_root = nullptr, ev_csr = nullptr;
    if (!s_csr) {
        cudaStreamCreateWithFlags(&s_csr, cudaStreamNonBlocking);
        cudaEventCreateWithFlags(&ev_root, cudaEventDisableTiming);
        cudaEventCreateWithFlags(&ev_csr, cudaEventDisableTiming);
    }

    const int NB64 = N_NODES / 64;                          // 1250
    const int AGG_BLOCKS = (N_NODES / 2 * 32 + 255) / 256;  // 5000 (2 nodes/warp)

    cudaEventRecord(ev_root, (cudaStream_t)0);
    cudaStreamWaitEvent(s_csr, ev_root, 0);

    // Adjacency build on side stream, overlapped with layer-1 GEMM.
    k_zero_cnt<<<(N_NODES + 255) / 256, 256, 0, s_csr>>>();
    k_scatter<<<(N_EDGES + 255) / 256, 256, 0, s_csr>>>(ei);
    cudaEventRecord(ev_csr, s_csr);

    k_gemm1<<<NB64, 128>>>(x, W1);

    cudaStreamWaitEvent((cudaStream_t)0, ev_csr, 0);

    k_agg<true><<<AGG_BLOCKS, 256>>>(b1, dk[0][0], dk[0][1]);
    k_gemm2<<<NB64, 128>>>(W2);
    k_agg<false><<<AGG_BLOCKS, 256>>>(b2, dk[1][0], dk[1][1]);
    k_gemm2<<<NB64, 128>>>(W3);
    k_agg<false><<<AGG_BLOCKS, 256>>>(b3, dk[2][0], dk[2][1]);

    k_pool<<<64, 256>>>(batch);
    k_head<<<1, 1024>>>(Wm1, bm1, Wm2, bm2, out, dk[3][0], dk[3][1]);

    (void)in_sizes; (void)n_in; (void)out_size;
}

// round 12
// speedup vs baseline: 1.0999x; 1.0363x over previous
#include <cuda_runtime.h>
#include <cuda_bf16.h>
#include <cstdint>

#define N_NODES 80000
#define N_EDGES 1280000
#define HID     64
#define MAXDEG  64

// ---------------- device scratch (no allocations allowed) ----------------
__device__ int   d_cnt[N_NODES];
__device__ __align__(16) int d_col[N_NODES * MAXDEG];   // fixed-width adjacency
__device__ __align__(16) float d_g[N_NODES * HID];      // GEMM out, fp32 natural order
__device__ __align__(16) float d_h[N_NODES * HID];      // agg out, fp32 natural order
__device__ float d_pooled[64 * 64];                     // per-graph SUMS (natural)

// ---------------- threefry-2x32 (JAX partitionable semantics) ----------------
__device__ __forceinline__ uint2 threefry_dev(unsigned k0, unsigned k1,
                                              unsigned c0, unsigned c1) {
    unsigned ks2 = k0 ^ k1 ^ 0x1BD11BDAu;
    unsigned x0 = c0 + k0, x1 = c1 + k1;
#define TF_RND(r) { x0 += x1; x1 = __funnelshift_l(x1, x1, (r)); x1 ^= x0; }
    TF_RND(13) TF_RND(15) TF_RND(26) TF_RND(6)   x0 += k1;  x1 += ks2 + 1u;
    TF_RND(17) TF_RND(29) TF_RND(16) TF_RND(24)  x0 += ks2; x1 += k0 + 2u;
    TF_RND(13) TF_RND(15) TF_RND(26) TF_RND(6)   x0 += k0;  x1 += k1 + 3u;
    TF_RND(17) TF_RND(29) TF_RND(16) TF_RND(24)  x0 += k1;  x1 += ks2 + 4u;
    TF_RND(13) TF_RND(15) TF_RND(26) TF_RND(6)   x0 += ks2; x1 += k0 + 5u;
#undef TF_RND
    return make_uint2(x0, x1);
}

// keep = u < 0.7f, exact integer form: bits < 5872026*512.
__device__ __forceinline__ bool keep_elem(unsigned k0, unsigned k1, unsigned idx) {
    uint2 r = threefry_dev(k0, k1, 0u, idx);
    return (r.x ^ r.y) < 3006477312u;
}

// ---------------- adjacency build: zero + direct scatter ----------------
__global__ void k_zero_cnt() {
    int i = blockIdx.x * 256 + threadIdx.x;
    if (i < N_NODES) d_cnt[i] = 0;
    if (i < 4096) d_pooled[i] = 0.0f;   // pool sums re-zeroed each replay
}
__global__ void k_scatter(const int* __restrict__ ei) {
    int e = blockIdx.x * 256 + threadIdx.x;
    if (e < N_EDGES) {
        int src = ei[e];
        int dst = ei[N_EDGES + e];
        int pos = atomicAdd(&d_cnt[dst], 1);
        if (pos < MAXDEG) d_col[dst * MAXDEG + pos] = src;
    }
}

// ---------------- Layer-1 GEMM: g = X @ W1 (unscaled), fp32 natural ----------
__global__ void __launch_bounds__(128) k_gemm1(const float* __restrict__ X,
                                               const float* __restrict__ W) {
    __shared__ float  Xs[64][68];
    __shared__ float2 Ws[64][32];
    const int tid = threadIdx.x;
    const int rowBase = blockIdx.x * 64;
    const int tx = tid & 7, ty = tid >> 3;
    const int p0 = tx * 4, r0 = ty * 4;
    unsigned long long acc[4][4];
#pragma unroll
    for (int i = 0; i < 4; i++)
#pragma unroll
        for (int j = 0; j < 4; j++) acc[i][j] = 0ull;

    for (int kb = 0; kb < 128; kb += 64) {
#pragma unroll
        for (int t = 0; t < 32; t++) {
            int idx = tid + t * 128;
            int row = idx >> 6, kk = idx & 63;
            Xs[row][kk] = X[(size_t)(rowBase + row) * 128 + kb + kk];
        }
#pragma unroll
        for (int t = 0; t < 16; t++) {
            int idx = tid + t * 128;
            int kk = idx >> 5, p = idx & 31;
            int krow = kb + kk;
            Ws[kk][p] = make_float2(W[krow * 64 + 2 * p], W[krow * 64 + 2 * p + 1]);
        }
        __syncthreads();
#pragma unroll 8
        for (int kk = 0; kk < 64; ++kk) {
            ulonglong2 wA = *reinterpret_cast<const ulonglong2*>(&Ws[kk][p0]);
            ulonglong2 wB = *reinterpret_cast<const ulonglong2*>(&Ws[kk][p0 + 2]);
#pragma unroll
            for (int i = 0; i < 4; i++) {
                float x = Xs[r0 + i][kk];
                unsigned long long xp;
                asm("mov.b64 %0, {%1, %1};" : "=l"(xp) : "f"(x));
                asm("fma.rn.f32x2 %0, %1, %2, %0;" : "+l"(acc[i][0]) : "l"(xp), "l"(wA.x));
                asm("fma.rn.f32x2 %0, %1, %2, %0;" : "+l"(acc[i][1]) : "l"(xp), "l"(wA.y));
                asm("fma.rn.f32x2 %0, %1, %2, %0;" : "+l"(acc[i][2]) : "l"(xp), "l"(wB.x));
                asm("fma.rn.f32x2 %0, %1, %2, %0;" : "+l"(acc[i][3]) : "l"(xp), "l"(wB.y));
            }
        }
        __syncthreads();
    }
#pragma unroll
    for (int i = 0; i < 4; i++) {
        int row = rowBase + r0 + i;
        float f[8];
#pragma unroll
        for (int j = 0; j < 4; j++)
            asm("mov.b64 {%0, %1}, %2;" : "=f"(f[2 * j]), "=f"(f[2 * j + 1]) : "l"(acc[i][j]));
        *reinterpret_cast<float4*>(&d_g[row * 64 + 2 * p0]) =
            make_float4(f[0], f[1], f[2], f[3]);
        *reinterpret_cast<float4*>(&d_g[row * 64 + 2 * p0 + 4]) =
            make_float4(f[4], f[5], f[6], f[7]);
    }
}

// ---------------- Layer-2/3 GEMM: g = (d_h @ W) * dinv, fp32 natural ---------
__global__ void __launch_bounds__(128) k_gemm2(const float* __restrict__ W) {
    __shared__ float  Xs[64][68];
    __shared__ float2 Ws[64][32];
    const float* __restrict__ X = d_h;
    const int tid = threadIdx.x;
    const int rowBase = blockIdx.x * 64;
    const int tx = tid & 7, ty = tid >> 3;
    const int p0 = tx * 4, r0 = ty * 4;
    unsigned long long acc[4][4];
#pragma unroll
    for (int i = 0; i < 4; i++)
#pragma unroll
        for (int j = 0; j < 4; j++) acc[i][j] = 0ull;

#pragma unroll
    for (int t = 0; t < 32; t++) {
        int idx = tid + t * 128;
        int row = idx >> 6, kk = idx & 63;
        Xs[row][kk] = X[(size_t)(rowBase + row) * 64 + kk];
    }
#pragma unroll
    for (int t = 0; t < 16; t++) {
        int idx = tid + t * 128;
        int kk = idx >> 5, p = idx & 31;
        Ws[kk][p] = make_float2(W[kk * 64 + 2 * p], W[kk * 64 + 2 * p + 1]);
    }
    __syncthreads();
#pragma unroll 8
    for (int kk = 0; kk < 64; ++kk) {
        ulonglong2 wA = *reinterpret_cast<const ulonglong2*>(&Ws[kk][p0]);
        ulonglong2 wB = *reinterpret_cast<const ulonglong2*>(&Ws[kk][p0 + 2]);
#pragma unroll
        for (int i = 0; i < 4; i++) {
            float x = Xs[r0 + i][kk];
            unsigned long long xp;
            asm("mov.b64 %0, {%1, %1};" : "=l"(xp) : "f"(x));
            asm("fma.rn.f32x2 %0, %1, %2, %0;" : "+l"(acc[i][0]) : "l"(xp), "l"(wA.x));
            asm("fma.rn.f32x2 %0, %1, %2, %0;" : "+l"(acc[i][1]) : "l"(xp), "l"(wA.y));
            asm("fma.rn.f32x2 %0, %1, %2, %0;" : "+l"(acc[i][2]) : "l"(xp), "l"(wB.x));
            asm("fma.rn.f32x2 %0, %1, %2, %0;" : "+l"(acc[i][3]) : "l"(xp), "l"(wB.y));
        }
    }
#pragma unroll
    for (int i = 0; i < 4; i++) {
        int row = rowBase + r0 + i;
        float di = rsqrtf((float)d_cnt[row] + 1.0f);
        float f[8];
#pragma unroll
        for (int j = 0; j < 4; j++) {
            float lo, hi;
            asm("mov.b64 {%0, %1}, %2;" : "=f"(lo), "=f"(hi) : "l"(acc[i][j]));
            f[2 * j] = lo * di; f[2 * j + 1] = hi * di;
        }
        *reinterpret_cast<float4*>(&d_g[row * 64 + 2 * p0]) =
            make_float4(f[0], f[1], f[2], f[3]);
        *reinterpret_cast<float4*>(&d_g[row * 64 + 2 * p0 + 4]) =
            make_float4(f[4], f[5], f[6], f[7]);
    }
}

// ---------------- Aggregation + bias + ReLU + inline dropout (layers 1,2) ----
// 2 nodes per warp: lanes 0-15 -> node 2w, lanes 16-31 -> node 2w+1.
template <bool FIRST>
__global__ void __launch_bounds__(256) k_agg(const float* __restrict__ bias,
                                             unsigned k0, unsigned k1) {
    int gw = (blockIdx.x * 256 + threadIdx.x) >> 5;
    int lane = threadIdx.x & 31;
    int v = gw * 2 + (lane >> 4);
    int c0 = (lane & 15) * 4;

    int cntv = d_cnt[v];
    int deg = min(cntv, MAXDEG);
    float dv = rsqrtf((float)cntv + 1.0f);
    const int* __restrict__ cols = &d_col[(size_t)v * MAXDEG];

    float4 acc = *reinterpret_cast<const float4*>(&d_g[v * 64 + c0]);
    if (FIRST) { acc.x *= dv; acc.y *= dv; acc.z *= dv; acc.w *= dv; }

    int j = 0;
    for (; j + 4 <= deg; j += 4) {
        int4 c4 = *reinterpret_cast<const int4*>(&cols[j]);
        float4 t0 = *reinterpret_cast<const float4*>(&d_g[c4.x * 64 + c0]);
        float4 t1 = *reinterpret_cast<const float4*>(&d_g[c4.y * 64 + c0]);
        float4 t2 = *reinterpret_cast<const float4*>(&d_g[c4.z * 64 + c0]);
        float4 t3 = *reinterpret_cast<const float4*>(&d_g[c4.w * 64 + c0]);
        if (FIRST) {
            float du0 = rsqrtf((float)d_cnt[c4.x] + 1.0f);
            float du1 = rsqrtf((float)d_cnt[c4.y] + 1.0f);
            float du2 = rsqrtf((float)d_cnt[c4.z] + 1.0f);
            float du3 = rsqrtf((float)d_cnt[c4.w] + 1.0f);
            acc.x = fmaf(t0.x, du0, acc.x); acc.y = fmaf(t0.y, du0, acc.y);
            acc.z = fmaf(t0.z, du0, acc.z); acc.w = fmaf(t0.w, du0, acc.w);
            acc.x = fmaf(t1.x, du1, acc.x); acc.y = fmaf(t1.y, du1, acc.y);
            acc.z = fmaf(t1.z, du1, acc.z); acc.w = fmaf(t1.w, du1, acc.w);
            acc.x = fmaf(t2.x, du2, acc.x); acc.y = fmaf(t2.y, du2, acc.y);
            acc.z = fmaf(t2.z, du2, acc.z); acc.w = fmaf(t2.w, du2, acc.w);
            acc.x = fmaf(t3.x, du3, acc.x); acc.y = fmaf(t3.y, du3, acc.y);
            acc.z = fmaf(t3.z, du3, acc.z); acc.w = fmaf(t3.w, du3, acc.w);
        } else {
            acc.x += (t0.x + t1.x) + (t2.x + t3.x);
            acc.y += (t0.y + t1.y) + (t2.y + t3.y);
            acc.z += (t0.z + t1.z) + (t2.z + t3.z);
            acc.w += (t0.w + t1.w) + (t2.w + t3.w);
        }
    }
    for (; j < deg; ++j) {
        int u = cols[j];
        float4 t = *reinterpret_cast<const float4*>(&d_g[u * 64 + c0]);
        if (FIRST) {
            float du = rsqrtf((float)d_cnt[u] + 1.0f);
            acc.x = fmaf(t.x, du, acc.x); acc.y = fmaf(t.y, du, acc.y);
            acc.z = fmaf(t.z, du, acc.z); acc.w = fmaf(t.w, du, acc.w);
        } else {
            acc.x += t.x; acc.y += t.y; acc.z += t.z; acc.w += t.w;
        }
    }

    float4 b4 = *reinterpret_cast<const float4*>(&bias[c0]);
    float o0 = fmaxf(fmaf(dv, acc.x, b4.x), 0.0f);
    float o1 = fmaxf(fmaf(dv, acc.y, b4.y), 0.0f);
    float o2 = fmaxf(fmaf(dv, acc.z, b4.z), 0.0f);
    float o3 = fmaxf(fmaf(dv, acc.w, b4.w), 0.0f);

    unsigned i0 = (unsigned)v * 64u + (unsigned)c0;
    const float inv_keep = 1.0f / 0.7f;
    float4 hv;
    hv.x = keep_elem(k0, k1, i0)      ? o0 * inv_keep : 0.0f;
    hv.y = keep_elem(k0, k1, i0 + 1u) ? o1 * inv_keep : 0.0f;
    hv.z = keep_elem(k0, k1, i0 + 2u) ? o2 * inv_keep : 0.0f;
    hv.w = keep_elem(k0, k1, i0 + 3u) ? o3 * inv_keep : 0.0f;
    *reinterpret_cast<float4*>(&d_h[v * 64 + c0]) = hv;
}

// ---------------- Layer-3 agg fused with mean-pool accumulation --------------
// Same agg body (prescaled input), but instead of writing d_h, accumulate into
// per-block smem (<=2 graphs per 16-node block w.h.p.), flush via atomics.
__global__ void __launch_bounds__(256) k_aggpool(const float* __restrict__ bias,
                                                 const int* __restrict__ batch,
                                                 unsigned k0, unsigned k1) {
    __shared__ float accA[64], accB[64];
    __shared__ int gAB[2];
    int tid = threadIdx.x;
    if (tid < 64) accA[tid] = 0.0f;
    else if (tid < 128) accB[tid - 64] = 0.0f;
    int rowBase = blockIdx.x * 16;
    if (tid == 0) { gAB[0] = batch[rowBase]; gAB[1] = batch[rowBase + 15]; }
    __syncthreads();

    int gw = (blockIdx.x * 256 + tid) >> 5;
    int lane = tid & 31;
    int v = gw * 2 + (lane >> 4);
    int c0 = (lane & 15) * 4;

    int cntv = d_cnt[v];
    int deg = min(cntv, MAXDEG);
    float dv = rsqrtf((float)cntv + 1.0f);
    const int* __restrict__ cols = &d_col[(size_t)v * MAXDEG];

    float4 acc = *reinterpret_cast<const float4*>(&d_g[v * 64 + c0]);
    int j = 0;
    for (; j + 4 <= deg; j += 4) {
        int4 c4 = *reinterpret_cast<const int4*>(&cols[j]);
        float4 t0 = *reinterpret_cast<const float4*>(&d_g[c4.x * 64 + c0]);
        float4 t1 = *reinterpret_cast<const float4*>(&d_g[c4.y * 64 + c0]);
        float4 t2 = *reinterpret_cast<const float4*>(&d_g[c4.z * 64 + c0]);
        float4 t3 = *reinterpret_cast<const float4*>(&d_g[c4.w * 64 + c0]);
        acc.x += (t0.x + t1.x) + (t2.x + t3.x);
        acc.y += (t0.y + t1.y) + (t2.y + t3.y);
        acc.z += (t0.z + t1.z) + (t2.z + t3.z);
        acc.w += (t0.w + t1.w) + (t2.w + t3.w);
    }
    for (; j < deg; ++j) {
        int u = cols[j];
        float4 t = *reinterpret_cast<const float4*>(&d_g[u * 64 + c0]);
        acc.x += t.x; acc.y += t.y; acc.z += t.z; acc.w += t.w;
    }

    float4 b4 = *reinterpret_cast<const float4*>(&bias[c0]);
    float o0 = fmaxf(fmaf(dv, acc.x, b4.x), 0.0f);
    float o1 = fmaxf(fmaf(dv, acc.y, b4.y), 0.0f);
    float o2 = fmaxf(fmaf(dv, acc.z, b4.z), 0.0f);
    float o3 = fmaxf(fmaf(dv, acc.w, b4.w), 0.0f);

    unsigned i0 = (unsigned)v * 64u + (unsigned)c0;
    const float inv_keep = 1.0f / 0.7f;
    float h0 = keep_elem(k0, k1, i0)      ? o0 * inv_keep : 0.0f;
    float h1 = keep_elem(k0, k1, i0 + 1u) ? o1 * inv_keep : 0.0f;
    float h2 = keep_elem(k0, k1, i0 + 2u) ? o2 * inv_keep : 0.0f;
    float h3 = keep_elem(k0, k1, i0 + 3u) ? o3 * inv_keep : 0.0f;

    int g = batch[v];
    int gA = gAB[0], gB = gAB[1];
    if (g == gA) {
        atomicAdd(&accA[c0],     h0); atomicAdd(&accA[c0 + 1], h1);
        atomicAdd(&accA[c0 + 2], h2); atomicAdd(&accA[c0 + 3], h3);
    } else if (g == gB) {
        atomicAdd(&accB[c0],     h0); atomicAdd(&accB[c0 + 1], h1);
        atomicAdd(&accB[c0 + 2], h2); atomicAdd(&accB[c0 + 3], h3);
    } else {  // vanishingly rare: >2 graphs in a 16-node block
        atomicAdd(&d_pooled[g * 64 + c0],     h0);
        atomicAdd(&d_pooled[g * 64 + c0 + 1], h1);
        atomicAdd(&d_pooled[g * 64 + c0 + 2], h2);
        atomicAdd(&d_pooled[g * 64 + c0 + 3], h3);
    }
    __syncthreads();
    if (tid < 64) atomicAdd(&d_pooled[gA * 64 + tid], accA[tid]);
    else if (tid < 128 && gAB[1] != gAB[0])
        atomicAdd(&d_pooled[gAB[1] * 64 + (tid - 64)], accB[tid - 64]);
}

// ---------------- MLP head: normalize sums -> means, then Linear stack -------
__global__ void k_head(const int* __restrict__ batch,
                       const float* __restrict__ Wm1, const float* __restrict__ bm1,
                       const float* __restrict__ Wm2, const float* __restrict__ bm2,
                       float* __restrict__ out, unsigned k0, unsigned k1) {
    __shared__ float Ps[64][64];
    __shared__ float Ws[64][64];
    __shared__ int   se[65];
    int tid = threadIdx.x;
    if (tid <= 64) {
        int target = tid;   // lower_bound(batch, target)
        int lo = 0, hi = N_NODES;
        while (lo < hi) { int m = (lo + hi) >> 1; if (batch[m] < target) lo = m + 1; else hi = m; }
        se[tid] = lo;
    }
    for (int idx = tid; idx < 4096; idx += 1024)
        Ps[idx >> 6][idx & 63] = d_pooled[idx];
    for (int idx = tid; idx < 4096; idx += 1024)
        Ws[idx >> 6][idx & 63] = Wm1[idx];
    __syncthreads();
    // sums -> means
    for (int idx = tid; idx < 4096; idx += 1024) {
        int g = idx >> 6;
        float cnt = fmaxf((float)(se[g + 1] - se[g]), 1.0f);
        Ps[g][idx & 63] *= (1.0f / cnt);
    }
    __syncthreads();

    int c = tid & 63, gb = tid >> 6;
    float mv[2][2];
#pragma unroll
    for (int halfg = 0; halfg < 2; ++halfg) {
        int g = gb + halfg * 16;
        float mA = bm1[c], mB = bm1[c];
#pragma unroll
        for (int s = 0; s < 64; s++) {
            mA = fmaf(Ps[g][s], Ws[s][c], mA);
            mB = fmaf(Ps[g + 32][s], Ws[s][c], mB);
        }
        mA = fmaxf(mA, 0.0f);
        mB = fmaxf(mB, 0.0f);
        unsigned iA = (unsigned)g * 64u + (unsigned)c;
        unsigned iB = (unsigned)(g + 32) * 64u + (unsigned)c;
        const float inv_keep = 1.0f / 0.7f;
        mv[halfg][0] = keep_elem(k0, k1, iA) ? mA * inv_keep : 0.0f;
        mv[halfg][1] = keep_elem(k0, k1, iB) ? mB * inv_keep : 0.0f;
    }
    __syncthreads();
#pragma unroll
    for (int halfg = 0; halfg < 2; ++halfg) {
        int g = gb + halfg * 16;
        Ps[g][c] = mv[halfg][0];
        Ps[g + 32][c] = mv[halfg][1];
    }
    __syncthreads();
    if (tid < 64) {
        float o = bm2[0];
#pragma unroll
        for (int cc = 0; cc < 64; ++cc) o = fmaf(Ps[tid][cc], Wm2[cc], o);
        out[tid] = o;
    }
}

// ---------------- host threefry (key splitting) ----------------
static inline void tf_host(unsigned k0, unsigned k1, unsigned c0, unsigned c1,
                           unsigned& o0, unsigned& o1) {
    unsigned ks2 = k0 ^ k1 ^ 0x1BD11BDAu;
    unsigned x0 = c0 + k0, x1 = c1 + k1;
#define HROT(x, r) (((x) << (r)) | ((x) >> (32 - (r))))
#define HRND(r) { x0 += x1; x1 = HROT(x1, r); x1 ^= x0; }
    HRND(13) HRND(15) HRND(26) HRND(6)   x0 += k1;  x1 += ks2 + 1u;
    HRND(17) HRND(29) HRND(16) HRND(24)  x0 += ks2; x1 += k0 + 2u;
    HRND(13) HRND(15) HRND(26) HRND(6)   x0 += k0;  x1 += k1 + 3u;
    HRND(17) HRND(29) HRND(16) HRND(24)  x0 += k1;  x1 += ks2 + 4u;
    HRND(13) HRND(15) HRND(26) HRND(6)   x0 += ks2; x1 += k0 + 5u;
#undef HRND
#undef HROT
    o0 = x0; o1 = x1;
}

extern "C" void kernel_launch(void* const* d_in, const int* in_sizes, int n_in,
                              void* d_out, int out_size) {
    const float* x     = (const float*)d_in[0];
    const int*   ei    = (const int*)d_in[1];
    const int*   batch = (const int*)d_in[2];
    const float* W1 = (const float*)d_in[3];  const float* b1 = (const float*)d_in[4];
    const float* W2 = (const float*)d_in[5];  const float* b2 = (const float*)d_in[6];
    const float* W3 = (const float*)d_in[7];  const float* b3 = (const float*)d_in[8];
    const float* Wm1 = (const float*)d_in[9]; const float* bm1 = (const float*)d_in[10];
    const float* Wm2 = (const float*)d_in[11];const float* bm2 = (const float*)d_in[12];
    float* out = (float*)d_out;

    // split(key(42), 4) partitionable: dk[i] = threefry((0,42), (0, i))
    unsigned dk[4][2];
    for (unsigned i = 0; i < 4; i++)
        tf_host(0u, 42u, 0u, i, dk[i][0], dk[i][1]);

    static cudaStream_t s_csr = nullptr;
    static cudaEvent_t ev_root = nullptr, ev_csr = nullptr;
    if (!s_csr) {
        cudaStreamCreateWithFlags(&s_csr, cudaStreamNonBlocking);
        cudaEventCreateWithFlags(&ev_root, cudaEventDisableTiming);
        cudaEventCreateWithFlags(&ev_csr, cudaEventDisableTiming);
    }

    const int NB64 = N_NODES / 64;                          // 1250
    const int AGG_BLOCKS = (N_NODES / 2 * 32 + 255) / 256;  // 5000 (2 nodes/warp)

    cudaEventRecord(ev_root, (cudaStream_t)0);
    cudaStreamWaitEvent(s_csr, ev_root, 0);

    // Adjacency build (+ pool-sum zeroing) on side stream, overlapped with GEMM1.
    k_zero_cnt<<<(N_NODES + 255) / 256, 256, 0, s_csr>>>();
    k_scatter<<<(N_EDGES + 255) / 256, 256, 0, s_csr>>>(ei);
    cudaEventRecord(ev_csr, s_csr);

    k_gemm1<<<NB64, 128>>>(x, W1);

    cudaStreamWaitEvent((cudaStream_t)0, ev_csr, 0);

    k_agg<true><<<AGG_BLOCKS, 256>>>(b1, dk[0][0], dk[0][1]);
    k_gemm2<<<NB64, 128>>>(W2);
    k_agg<false><<<AGG_BLOCKS, 256>>>(b2, dk[1][0], dk[1][1]);
    k_gemm2<<<NB64, 128>>>(W3);
    k_aggpool<<<AGG_BLOCKS, 256>>>(b3, batch, dk[2][0], dk[2][1]);

    k_head<<<1, 1024>>>(batch, Wm1, bm1, Wm2, bm2, out, dk[3][0], dk[3][1]);

    (void)in_sizes; (void)n_in; (void)out_size;
}